// round 12
// baseline (speedup 1.0000x reference)
#include <cuda_runtime.h>
#include <math.h>

#define NF 256
#define NS 65536
#define NC 2000
#define NCP 2048
#define NB 256
#define CAP 128
#define TEMPv 0.05f
#define INS_TEMPv 0.09f

// sim tile config
#define TC 64          // classes per block
#define TB 32          // samples per block
#define KC 32          // k chunk
#define SIM_BLOCKS ((NCP / TC) * (NB / TB))   // 32 x 8 = 256

// ---- scratch (device globals; all zero-init; reset by k_final each run) ----
__device__ int   g_cnt1[NCP];
__device__ int   g_cnt2[NCP];
__device__ int2  g_list1[NC * CAP];        // (index, labels2[index])
__device__ int2  g_list2[NC * CAP];        // (index, labels[index])
__device__ int   g_targ[NB];
__device__ int   g_targ2[NB];
__device__ float g_centT[NF * NCP];        // [k][c]: scaled centroids (c>=NC stays 0)
__device__ float g_inT[NF * NB];           // [k][b]: transposed inputs
__device__ float g_fsum[NB];
__device__ float g_ftgt[NB];
__device__ float g_ins;

// ---- K1: scatter into fixed-capacity buckets + transpose inputs + targets ----
__global__ void k_scatter(const int* __restrict__ labels, const int* __restrict__ labels2,
                          const float* __restrict__ inputs, const int* __restrict__ indexes) {
    int i = blockIdx.x * blockDim.x + threadIdx.x;
    int c1 = labels[i];
    int c2 = labels2[i];
    int p1 = atomicAdd(&g_cnt1[c1], 1);
    if (p1 < CAP) g_list1[c1 * CAP + p1] = make_int2(i, c2);
    int p2 = atomicAdd(&g_cnt2[c2], 1);
    if (p2 < CAP) g_list2[c2 * CAP + p2] = make_int2(i, c1);
    int b = i >> 8, k = i & 255;
    g_inT[k * NB + b] = inputs[i];
    if (i < NB) {
        int idx = indexes[i];
        g_targ[i]  = labels[idx];
        g_targ2[i] = labels2[idx];
    }
}

// ---- K2: scaled class centroids (one block per class) -> [k][c] layout ----
__global__ void k_centroid(const float* __restrict__ features) {
    int c   = blockIdx.x;
    int tid = threadIdx.x;
    int r   = tid >> 6;        // 0..7 row slot
    int f4  = tid & 63;        // float4 column
    int cnt = min(g_cnt1[c], CAP);
    __shared__ int js[CAP];
    if (tid < cnt) js[tid] = g_list1[c * CAP + tid].x;
    __syncthreads();
    float4 acc = make_float4(0.f, 0.f, 0.f, 0.f);
    int k = r;
    if (k < cnt) {
        float4 v0 = ((const float4*)(features + (size_t)js[k] * NF))[f4];
        for (k += 8; k < cnt; k += 8) {
            float4 v1 = ((const float4*)(features + (size_t)js[k] * NF))[f4];
            acc.x += v0.x; acc.y += v0.y; acc.z += v0.z; acc.w += v0.w;
            v0 = v1;
        }
        acc.x += v0.x; acc.y += v0.y; acc.z += v0.z; acc.w += v0.w;
    }
    __shared__ float4 sred[8][64];
    sred[r][f4] = acc;
    __syncthreads();
    if (r == 0) {
        float4 s = acc;
#pragma unroll
        for (int w = 1; w < 8; w++) {
            float4 a = sred[w][f4];
            s.x += a.x; s.y += a.y; s.z += a.z; s.w += a.w;
        }
        float sc = (cnt > 0) ? (1.f / (TEMPv * (float)cnt)) : 0.f;
        // [k][c] layout: 4 scalar stores, stride NCP floats
        g_centT[(4 * f4 + 0) * NCP + c] = s.x * sc;
        g_centT[(4 * f4 + 1) * NCP + c] = s.y * sc;
        g_centT[(4 * f4 + 2) * NCP + c] = s.z * sc;
        g_centT[(4 * f4 + 3) * NCP + c] = s.w * sc;
    }
}

// ---- K3: register-tiled sim GEMM + masked-softmax partials ----
// grid 256 = 32 c-tiles x 8 b-tiles; block 128 = 16 c-lanes x 8 b-lanes;
// thread tile 4c x 4b (2 B/MAC smem traffic), f32x2 accumulators.
__global__ void __launch_bounds__(128) k_simfocal() {
    __shared__ float sc_[KC][TC];       // 8 KB  (reused as ered in epilogue)
    __shared__ float sx_[KC][TB];       // 4 KB
    int tid = threadIdx.x;
    int bc  = blockIdx.x & 31;          // c-tile
    int bb  = blockIdx.x >> 5;          // b-tile
    int cx  = tid & 15;                 // c-lane
    int by  = tid >> 4;                 // b-lane (0..7)
    int c0  = bc * TC + cx * 4;
    int b0  = bb * TB + by * 4;

    unsigned long long acc2[4][2];      // [c][b-pair]
#pragma unroll
    for (int i = 0; i < 4; i++) { acc2[i][0] = 0ULL; acc2[i][1] = 0ULL; }

    for (int kc0 = 0; kc0 < NF; kc0 += KC) {
        // load cent chunk: KC x TC floats = 512 float4, 4 per thread (coalesced)
#pragma unroll
        for (int t = 0; t < 4; t++) {
            int idx = tid + t * 128;
            int row = idx >> 4, c4 = idx & 15;
            ((float4*)sc_[row])[c4] =
                *(const float4*)(g_centT + (size_t)(kc0 + row) * NCP + bc * TC + c4 * 4);
        }
        // load x chunk: KC x TB floats = 256 float4, 2 per thread (coalesced)
#pragma unroll
        for (int t = 0; t < 2; t++) {
            int idx = tid + t * 128;
            int row = idx >> 3, b4 = idx & 7;
            ((float4*)sx_[row])[b4] =
                *(const float4*)(g_inT + (size_t)(kc0 + row) * NB + bb * TB + b4 * 4);
        }
        __syncthreads();
#pragma unroll 8
        for (int k = 0; k < KC; k++) {
            float4 cv = *(const float4*)&sc_[k][cx * 4];                  // LDS.128
            unsigned long long xp0 = *(const unsigned long long*)&sx_[k][by * 4];     // LDS.64
            unsigned long long xp1 = *(const unsigned long long*)&sx_[k][by * 4 + 2]; // LDS.64
            float cs[4] = {cv.x, cv.y, cv.z, cv.w};
#pragma unroll
            for (int i = 0; i < 4; i++) {
                unsigned int cu = __float_as_uint(cs[i]);
                unsigned long long cc;
                asm("mov.b64 %0, {%1, %1};" : "=l"(cc) : "r"(cu));
                asm("fma.rn.f32x2 %0, %1, %2, %0;" : "+l"(acc2[i][0]) : "l"(cc), "l"(xp0));
                asm("fma.rn.f32x2 %0, %1, %2, %0;" : "+l"(acc2[i][1]) : "l"(cc), "l"(xp1));
            }
        }
        __syncthreads();
    }

    // ---- epilogue: masked exp, target extraction, per-b partial sums ----
    int nums[4], targ[4];
#pragma unroll
    for (int i = 0; i < 4; i++) nums[i] = g_cnt1[c0 + i];
#pragma unroll
    for (int j = 0; j < 4; j++) targ[j] = g_targ[b0 + j];

    float bsum[4] = {0.f, 0.f, 0.f, 0.f};
#pragma unroll
    for (int i = 0; i < 4; i++) {
        float s[4];
        union { unsigned long long u; float2 f; } a0, a1;
        a0.u = acc2[i][0]; a1.u = acc2[i][1];
        s[0] = a0.f.x; s[1] = a0.f.y; s[2] = a1.f.x; s[3] = a1.f.y;
        if (nums[i] > 0) {
            int c = c0 + i;
#pragma unroll
            for (int j = 0; j < 4; j++) {
                float e = expf(s[j]);        // cent pre-scaled by 1/(TEMP*nums)
                bsum[j] += e;
                if (c == targ[j]) g_ftgt[b0 + j] = e;   // unique writer
            }
        }
    }
    // reduce bsum over the 16 c-lanes: ered[cx][b] in reused sc_ smem
    float* ered = (float*)sc_;           // needs 16*TB floats = 2 KB
#pragma unroll
    for (int j = 0; j < 4; j++) ered[cx * TB + by * 4 + j] = bsum[j];
    __syncthreads();
    if (tid < TB) {
        float tot = 0.f;
#pragma unroll
        for (int w = 0; w < 16; w++) tot += ered[w * TB + tid];
        atomicAdd(&g_fsum[bb * TB + tid], tot);
    }
}

// ---- K4: ins loss (runs concurrently with centroid+simfocal) ----
__global__ void __launch_bounds__(512) k_ins(
        const float* __restrict__ inputs, const float* __restrict__ features) {
    int b   = blockIdx.x;
    int tid = threadIdx.x;
    int t   = g_targ[b];
    int t2  = g_targ2[b];
    __shared__ float4 inp[NF / 4];
    __shared__ int s_listA[CAP], s_listB[CAP];
    __shared__ int s_nA, s_nB;
    if (tid < NF / 4) inp[tid] = ((const float4*)(inputs + b * NF))[tid];
    if (tid == 0) { s_nA = 0; s_nB = 0; }
    __syncthreads();

    int cnt1 = min(g_cnt1[t], CAP);
    int cnt2 = min(g_cnt2[t2], CAP);
    if (tid < cnt1) {
        int2 e = g_list1[t * CAP + tid];
        if (e.y != t2) { int p = atomicAdd(&s_nA, 1); s_listA[p] = e.x; }
    }
    if (tid < cnt2) {
        int2 e = g_list2[t2 * CAP + tid];
        if (e.y != t) { int p = atomicAdd(&s_nB, 1); s_listB[p] = e.x; }
    }
    __syncthreads();
    int nA = s_nA, nB = s_nB;

    int lane = tid & 31, wid = tid >> 5;
    float4 u0 = inp[lane], u1 = inp[lane + 32];
    float pos = 0.f, neg = 0.f;
    {
        int i = wid;
        if (i < nA) {
            const float4* fr = (const float4*)(features + (size_t)s_listA[i] * NF);
            float4 f0 = fr[lane], f1 = fr[lane + 32];
            while (true) {
                int nx = i + 16;
                bool more = (nx < nA);
                float4 h0, h1;
                if (more) {
                    const float4* fn = (const float4*)(features + (size_t)s_listA[nx] * NF);
                    h0 = fn[lane]; h1 = fn[lane + 32];
                }
                float d = f0.x*u0.x + f0.y*u0.y + f0.z*u0.z + f0.w*u0.w
                        + f1.x*u1.x + f1.y*u1.y + f1.z*u1.z + f1.w*u1.w;
#pragma unroll
                for (int o = 16; o; o >>= 1) d += __shfl_xor_sync(0xFFFFFFFFu, d, o);
                pos += expf(d / INS_TEMPv);
                if (!more) break;
                i = nx; f0 = h0; f1 = h1;
            }
        }
    }
    {
        int i = wid;
        if (i < nB) {
            const float4* fr = (const float4*)(features + (size_t)s_listB[i] * NF);
            float4 f0 = fr[lane], f1 = fr[lane + 32];
            while (true) {
                int nx = i + 16;
                bool more = (nx < nB);
                float4 h0, h1;
                if (more) {
                    const float4* fn = (const float4*)(features + (size_t)s_listB[nx] * NF);
                    h0 = fn[lane]; h1 = fn[lane + 32];
                }
                float d = f0.x*u0.x + f0.y*u0.y + f0.z*u0.z + f0.w*u0.w
                        + f1.x*u1.x + f1.y*u1.y + f1.z*u1.z + f1.w*u1.w;
#pragma unroll
                for (int o = 16; o; o >>= 1) d += __shfl_xor_sync(0xFFFFFFFFu, d, o);
                neg += expf(d / INS_TEMPv);
                if (!more) break;
                i = nx; f0 = h0; f1 = h1;
            }
        }
    }

    __shared__ float rp[16], rn[16];
    if (lane == 0) { rp[wid] = pos; rn[wid] = neg; }
    __syncthreads();
    if (tid == 0) {
        float P = 0.f, Ng = 0.f;
#pragma unroll
        for (int w = 0; w < 16; w++) { P += rp[w]; Ng += rn[w]; }
        if (nA > 0 && nB > 0) {
            float insv = P / (P + Ng + 1e-6f);
            float per = -logf(insv + 1e-6f) / (float)nA;
            atomicAdd(&g_ins, per);
        }
    }
}

// ---- K5: final combine (after join) + full scratch reset for next replay ----
__global__ void k_final(const float* __restrict__ inputs, const float* __restrict__ mask_in,
                        const int* __restrict__ epoch_p, const int* __restrict__ back_p,
                        float* __restrict__ out) {
    int bb = threadIdx.x;
    float p  = g_ftgt[bb] / (g_fsum[bb] + 1e-6f);
    g_ftgt[bb] = 0.f; g_fsum[bb] = 0.f;
    float om = 1.f - p;
    float fb = -om * om * logf(p + 1e-6f);
    const float4* a = (const float4*)(inputs  + bb * NF);
    const float4* m = (const float4*)(mask_in + bb * NF);
    float na = 0.f, nm = 0.f, d = 0.f;
    for (int k = 0; k < NF / 4; k++) {
        float4 x = a[k], y = m[k];
        na += x.x*x.x + x.y*x.y + x.z*x.z + x.w*x.w;
        nm += y.x*y.x + y.y*y.y + y.z*y.z + y.w*y.w;
        d  += x.x*y.x + x.y*y.y + x.z*y.z + x.w*y.w;
    }
    float cv = d / (sqrtf(na) * sqrtf(nm));
    __shared__ float sf[NB], sc2[NB];
    sf[bb] = fb; sc2[bb] = cv;
    __syncthreads();
    for (int o = 128; o > 0; o >>= 1) {
        if (bb < o) { sf[bb] += sf[bb + o]; sc2[bb] += sc2[bb + o]; }
        __syncthreads();
    }
    for (int i = bb; i < NCP; i += 256) { g_cnt1[i] = 0; g_cnt2[i] = 0; }
    if (bb == 0) {
        float focal   = sf[0] / (float)NB;
        float contras = -sc2[0] / (float)NB;
        float insv    = g_ins / (float)NB;
        g_ins = 0.f;
        int epoch = epoch_p[0];
        int back  = back_p[0];
        float loss;
        if (back == 1) {
            loss = focal + 0.25f * contras;
            if (epoch >= 30) loss += 0.2f * insv;
        } else if (back == 2) {
            loss = focal + 0.25f * contras;
        } else {
            loss = focal;
        }
        out[0] = loss;
    }
}

extern "C" void kernel_launch(void* const* d_in, const int* in_sizes, int n_in,
                              void* d_out, int out_size) {
    const float* inputs   = (const float*)d_in[0];
    const float* mask_in  = (const float*)d_in[1];
    const float* features = (const float*)d_in[2];
    const int*   labels   = (const int*)d_in[3];
    const int*   labels2  = (const int*)d_in[4];
    const int*   indexes  = (const int*)d_in[5];
    const int*   epoch_p  = (const int*)d_in[6];
    const int*   back_p   = (const int*)d_in[7];
    float*       out      = (float*)d_out;

    // one-time host-side resources (no device memory involved)
    static cudaStream_t s_ins = nullptr;
    static cudaEvent_t  evFork = nullptr, evIns = nullptr;
    if (s_ins == nullptr) {
        cudaStreamCreateWithFlags(&s_ins, cudaStreamNonBlocking);
        cudaEventCreateWithFlags(&evFork, cudaEventDisableTiming);
        cudaEventCreateWithFlags(&evIns,  cudaEventDisableTiming);
    }

    k_scatter<<<NS / 256, 256>>>(labels, labels2, inputs, indexes);
    cudaEventRecord(evFork, 0);

    // ins branch (hidden under centroid+sim)
    cudaStreamWaitEvent(s_ins, evFork, 0);
    k_ins<<<NB, 512, 0, s_ins>>>(inputs, features);
    cudaEventRecord(evIns, s_ins);

    // main chain
    k_centroid<<<NC, 512>>>(features);
    k_simfocal<<<SIM_BLOCKS, 128>>>();

    // join + final combine
    cudaStreamWaitEvent(0, evIns, 0);
    k_final<<<1, 256>>>(inputs, mask_in, epoch_p, back_p, out);
}

// round 13
// speedup vs baseline: 1.1132x; 1.1132x over previous
#include <cuda_runtime.h>
#include <math.h>

#define NF 256
#define NS 65536
#define NC 2000
#define NCP 2048
#define NB 256
#define CAP 128
#define TEMPv 0.05f
#define INS_TEMPv 0.09f
#define GC 16
#define NGRP (NC / GC)        // 125 class groups
#define NGRP_A 63             // branch A: groups [0,63)   -> classes [0,1008)
#define NGRP_B 62             // branch B: groups [63,125) -> classes [1008,2000)
#define SIM_SMEM (16384 + 3 * 64 * 33 * 4)   // cent 16KB + split-k staging = 41728 B

// ---- scratch (device globals; all zero-init; reset by k_final each run) ----
__device__ int   g_cnt1[NCP];
__device__ int   g_cnt2[NCP];
__device__ int2  g_list1[NC * CAP];        // (index, labels2[index])
__device__ int2  g_list2[NC * CAP];        // (index, labels[index])
__device__ int   g_targ[NB];
__device__ int   g_targ2[NB];
__device__ float g_centT[NGRP * NF * GC];  // [grp][k][g]: scaled centroids, transposed
__device__ float g_in4[NF * NB];           // packed inputs: float4 (k/4)*NB + b
__device__ float g_fsum[NB];
__device__ float g_ftgt[NB];
__device__ float g_ins;

// ---- K1: scatter into fixed-capacity buckets + pack inputs + targets ----
__global__ void k_scatter(const int* __restrict__ labels, const int* __restrict__ labels2,
                          const float* __restrict__ inputs, const int* __restrict__ indexes) {
    int i = blockIdx.x * blockDim.x + threadIdx.x;
    int c1 = labels[i];
    int c2 = labels2[i];
    int p1 = atomicAdd(&g_cnt1[c1], 1);
    if (p1 < CAP) g_list1[c1 * CAP + p1] = make_int2(i, c2);
    int p2 = atomicAdd(&g_cnt2[c2], 1);
    if (p2 < CAP) g_list2[c2 * CAP + p2] = make_int2(i, c1);
    int b = i >> 8, k = i & 255;
    g_in4[(((k >> 2) * NB) + b) * 4 + (k & 3)] = inputs[i];
    if (i < NB) {
        int idx = indexes[i];
        g_targ[i]  = labels[idx];
        g_targ2[i] = labels2[idx];
    }
}

// ---- K2: scaled class centroids for class range [c0, c0+gridDim) ----
__global__ void k_centroid(const float* __restrict__ features, int c0) {
    int c   = c0 + blockIdx.x;
    int tid = threadIdx.x;
    int r   = tid >> 6;        // 0..7 row slot
    int f4  = tid & 63;        // float4 column
    int cnt = min(g_cnt1[c], CAP);
    __shared__ int js[CAP];
    if (tid < cnt) js[tid] = g_list1[c * CAP + tid].x;
    __syncthreads();
    float4 acc = make_float4(0.f, 0.f, 0.f, 0.f);
    int k = r;
    if (k < cnt) {
        float4 v0 = ((const float4*)(features + (size_t)js[k] * NF))[f4];
        for (k += 8; k < cnt; k += 8) {
            float4 v1 = ((const float4*)(features + (size_t)js[k] * NF))[f4];
            acc.x += v0.x; acc.y += v0.y; acc.z += v0.z; acc.w += v0.w;
            v0 = v1;
        }
        acc.x += v0.x; acc.y += v0.y; acc.z += v0.z; acc.w += v0.w;
    }
    __shared__ float4 sred[8][64];
    sred[r][f4] = acc;
    __syncthreads();
    if (r == 0) {
        float4 s = acc;
#pragma unroll
        for (int w = 1; w < 8; w++) {
            float4 a = sred[w][f4];
            s.x += a.x; s.y += a.y; s.z += a.z; s.w += a.w;
        }
        float sc = (cnt > 0) ? (1.f / (TEMPv * (float)cnt)) : 0.f;
        float* dst = g_centT + (size_t)(c >> 4) * (NF * GC) + (c & 15);
        dst[(4 * f4 + 0) * GC] = s.x * sc;
        dst[(4 * f4 + 1) * GC] = s.y * sc;
        dst[(4 * f4 + 2) * GC] = s.z * sc;
        dst[(4 * f4 + 3) * GC] = s.w * sc;
    }
}

// ---- K3: sim GEMM + masked-softmax partials ----
// grid = 2 * #groups (b-split); block 256 = 64 sample-pairs x 4 k-quarters.
// 2 samples/thread, 16 classes as f32x2 accumulators (2 B/MAC smem traffic).
__global__ void __launch_bounds__(256) k_simfocal(int cg0) {
    int cg  = cg0 + (blockIdx.x >> 1);
    int bq  = blockIdx.x & 1;
    extern __shared__ char sm[];
    float* cent = (float*)sm;                   // [k][g], 16 KB
    float* s_sk = (float*)(sm + 16384);         // split-k staging, stride 33
    int tid = threadIdx.x;
    int bl  = tid & 63;
    int kq  = tid >> 6;                         // 0..3
    int b0  = bq * 64 + bl;                     // 0..127
    int b1  = b0 + 128;

    const float4* src = (const float4*)(g_centT + (size_t)cg * (NF * GC));
    for (int t = tid; t < NF * GC / 4; t += 256) ((float4*)cent)[t] = src[t];
    __syncthreads();

    unsigned long long aA[8], aB[8];
#pragma unroll
    for (int q = 0; q < 8; q++) { aA[q] = 0ULL; aB[q] = 0ULL; }
    const float4* xp = (const float4*)g_in4;
    int k4beg = kq * 16;
#pragma unroll 2
    for (int k4 = k4beg; k4 < k4beg + 16; k4++) {
        float4 xA = xp[k4 * NB + b0];
        float4 xB = xp[k4 * NB + b1];
        float xsA[4] = {xA.x, xA.y, xA.z, xA.w};
        float xsB[4] = {xB.x, xB.y, xB.z, xB.w};
#pragma unroll
        for (int j = 0; j < 4; j++) {
            int k = 4 * k4 + j;
            unsigned long long xxA, xxB;
            unsigned int ua = __float_as_uint(xsA[j]);
            unsigned int ub = __float_as_uint(xsB[j]);
            asm("mov.b64 %0, {%1, %1};" : "=l"(xxA) : "r"(ua));
            asm("mov.b64 %0, {%1, %1};" : "=l"(xxB) : "r"(ub));
            const ulonglong2* cp = (const ulonglong2*)(cent + k * GC);
#pragma unroll
            for (int q = 0; q < 4; q++) {
                ulonglong2 cv = cp[q];          // LDS.128 broadcast
                asm("fma.rn.f32x2 %0, %1, %2, %0;" : "+l"(aA[2*q])   : "l"(cv.x), "l"(xxA));
                asm("fma.rn.f32x2 %0, %1, %2, %0;" : "+l"(aA[2*q+1]) : "l"(cv.y), "l"(xxA));
                asm("fma.rn.f32x2 %0, %1, %2, %0;" : "+l"(aB[2*q])   : "l"(cv.x), "l"(xxB));
                asm("fma.rn.f32x2 %0, %1, %2, %0;" : "+l"(aB[2*q+1]) : "l"(cv.y), "l"(xxB));
            }
        }
    }

    // ordered split-k combine (stride 33 floats: odd stride => conflict-free)
    if (kq) {
        float* dst = s_sk + ((kq - 1) * 64 + bl) * 33;
#pragma unroll
        for (int q = 0; q < 8; q++) {
            union { unsigned long long u; float2 f; } a, bv;
            a.u = aA[q]; bv.u = aB[q];
            dst[2*q]      = a.f.x;  dst[2*q + 1]      = a.f.y;
            dst[16 + 2*q] = bv.f.x; dst[16 + 2*q + 1] = bv.f.y;
        }
    }
    __syncthreads();
    if (kq == 0) {
        float sA[16], sB[16];
#pragma unroll
        for (int q = 0; q < 8; q++) {
            union { unsigned long long u; float2 f; } a, bv;
            a.u = aA[q]; bv.u = aB[q];
            sA[2*q] = a.f.x;  sA[2*q+1] = a.f.y;
            sB[2*q] = bv.f.x; sB[2*q+1] = bv.f.y;
        }
#pragma unroll
        for (int rr = 0; rr < 3; rr++) {
            const float* sp2 = s_sk + (rr * 64 + bl) * 33;
#pragma unroll
            for (int g = 0; g < 16; g++) { sA[g] += sp2[g]; sB[g] += sp2[16 + g]; }
        }
        int t0 = g_targ[b0], t1 = g_targ[b1];
        float l0 = 0.f, l1 = 0.f;
#pragma unroll
        for (int g = 0; g < GC; g++) {
            int c = cg * GC + g;
            if (g_cnt1[c] > 0) {
                float e0 = expf(sA[g]);
                float e1 = expf(sB[g]);
                l0 += e0; l1 += e1;
                if (c == t0) g_ftgt[b0] = e0;
                if (c == t1) g_ftgt[b1] = e1;
            }
        }
        atomicAdd(&g_fsum[b0], l0);
        atomicAdd(&g_fsum[b1], l1);
    }
}

// ---- K4: ins loss (runs concurrently with both centroid/sim branches) ----
__global__ void __launch_bounds__(512) k_ins(
        const float* __restrict__ inputs, const float* __restrict__ features) {
    int b   = blockIdx.x;
    int tid = threadIdx.x;
    int t   = g_targ[b];
    int t2  = g_targ2[b];
    __shared__ float4 inp[NF / 4];
    __shared__ int s_listA[CAP], s_listB[CAP];
    __shared__ int s_nA, s_nB;
    if (tid < NF / 4) inp[tid] = ((const float4*)(inputs + b * NF))[tid];
    if (tid == 0) { s_nA = 0; s_nB = 0; }
    __syncthreads();

    int cnt1 = min(g_cnt1[t], CAP);
    int cnt2 = min(g_cnt2[t2], CAP);
    if (tid < cnt1) {
        int2 e = g_list1[t * CAP + tid];
        if (e.y != t2) { int p = atomicAdd(&s_nA, 1); s_listA[p] = e.x; }
    }
    if (tid < cnt2) {
        int2 e = g_list2[t2 * CAP + tid];
        if (e.y != t) { int p = atomicAdd(&s_nB, 1); s_listB[p] = e.x; }
    }
    __syncthreads();
    int nA = s_nA, nB = s_nB;

    int lane = tid & 31, wid = tid >> 5;
    float4 u0 = inp[lane], u1 = inp[lane + 32];
    float pos = 0.f, neg = 0.f;
    {
        int i = wid;
        if (i < nA) {
            const float4* fr = (const float4*)(features + (size_t)s_listA[i] * NF);
            float4 f0 = fr[lane], f1 = fr[lane + 32];
            while (true) {
                int nx = i + 16;
                bool more = (nx < nA);
                float4 h0, h1;
                if (more) {
                    const float4* fn = (const float4*)(features + (size_t)s_listA[nx] * NF);
                    h0 = fn[lane]; h1 = fn[lane + 32];
                }
                float d = f0.x*u0.x + f0.y*u0.y + f0.z*u0.z + f0.w*u0.w
                        + f1.x*u1.x + f1.y*u1.y + f1.z*u1.z + f1.w*u1.w;
#pragma unroll
                for (int o = 16; o; o >>= 1) d += __shfl_xor_sync(0xFFFFFFFFu, d, o);
                pos += expf(d / INS_TEMPv);
                if (!more) break;
                i = nx; f0 = h0; f1 = h1;
            }
        }
    }
    {
        int i = wid;
        if (i < nB) {
            const float4* fr = (const float4*)(features + (size_t)s_listB[i] * NF);
            float4 f0 = fr[lane], f1 = fr[lane + 32];
            while (true) {
                int nx = i + 16;
                bool more = (nx < nB);
                float4 h0, h1;
                if (more) {
                    const float4* fn = (const float4*)(features + (size_t)s_listB[nx] * NF);
                    h0 = fn[lane]; h1 = fn[lane + 32];
                }
                float d = f0.x*u0.x + f0.y*u0.y + f0.z*u0.z + f0.w*u0.w
                        + f1.x*u1.x + f1.y*u1.y + f1.z*u1.z + f1.w*u1.w;
#pragma unroll
                for (int o = 16; o; o >>= 1) d += __shfl_xor_sync(0xFFFFFFFFu, d, o);
                neg += expf(d / INS_TEMPv);
                if (!more) break;
                i = nx; f0 = h0; f1 = h1;
            }
        }
    }

    __shared__ float rp[16], rn[16];
    if (lane == 0) { rp[wid] = pos; rn[wid] = neg; }
    __syncthreads();
    if (tid == 0) {
        float P = 0.f, Ng = 0.f;
#pragma unroll
        for (int w = 0; w < 16; w++) { P += rp[w]; Ng += rn[w]; }
        if (nA > 0 && nB > 0) {
            float insv = P / (P + Ng + 1e-6f);
            float per = -logf(insv + 1e-6f) / (float)nA;
            atomicAdd(&g_ins, per);
        }
    }
}

// ---- K5: final combine (after join) + full scratch reset for next replay ----
__global__ void k_final(const float* __restrict__ inputs, const float* __restrict__ mask_in,
                        const int* __restrict__ epoch_p, const int* __restrict__ back_p,
                        float* __restrict__ out) {
    int bb = threadIdx.x;
    float p  = g_ftgt[bb] / (g_fsum[bb] + 1e-6f);
    g_ftgt[bb] = 0.f; g_fsum[bb] = 0.f;
    float om = 1.f - p;
    float fb = -om * om * logf(p + 1e-6f);
    const float4* a = (const float4*)(inputs  + bb * NF);
    const float4* m = (const float4*)(mask_in + bb * NF);
    float na = 0.f, nm = 0.f, d = 0.f;
    for (int k = 0; k < NF / 4; k++) {
        float4 x = a[k], y = m[k];
        na += x.x*x.x + x.y*x.y + x.z*x.z + x.w*x.w;
        nm += y.x*y.x + y.y*y.y + y.z*y.z + y.w*y.w;
        d  += x.x*y.x + x.y*y.y + x.z*y.z + x.w*y.w;
    }
    float cv = d / (sqrtf(na) * sqrtf(nm));
    __shared__ float sf[NB], sc2[NB];
    sf[bb] = fb; sc2[bb] = cv;
    __syncthreads();
    for (int o = 128; o > 0; o >>= 1) {
        if (bb < o) { sf[bb] += sf[bb + o]; sc2[bb] += sc2[bb + o]; }
        __syncthreads();
    }
    for (int i = bb; i < NCP; i += 256) { g_cnt1[i] = 0; g_cnt2[i] = 0; }
    if (bb == 0) {
        float focal   = sf[0] / (float)NB;
        float contras = -sc2[0] / (float)NB;
        float insv    = g_ins / (float)NB;
        g_ins = 0.f;
        int epoch = epoch_p[0];
        int back  = back_p[0];
        float loss;
        if (back == 1) {
            loss = focal + 0.25f * contras;
            if (epoch >= 30) loss += 0.2f * insv;
        } else if (back == 2) {
            loss = focal + 0.25f * contras;
        } else {
            loss = focal;
        }
        out[0] = loss;
    }
}

extern "C" void kernel_launch(void* const* d_in, const int* in_sizes, int n_in,
                              void* d_out, int out_size) {
    const float* inputs   = (const float*)d_in[0];
    const float* mask_in  = (const float*)d_in[1];
    const float* features = (const float*)d_in[2];
    const int*   labels   = (const int*)d_in[3];
    const int*   labels2  = (const int*)d_in[4];
    const int*   indexes  = (const int*)d_in[5];
    const int*   epoch_p  = (const int*)d_in[6];
    const int*   back_p   = (const int*)d_in[7];
    float*       out      = (float*)d_out;

    // one-time host-side resources (no device memory involved)
    static cudaStream_t s_ins = nullptr, s_b = nullptr;
    static cudaEvent_t  evFork = nullptr, evIns = nullptr, evSB = nullptr;
    if (s_ins == nullptr) {
        cudaStreamCreateWithFlags(&s_ins, cudaStreamNonBlocking);
        cudaStreamCreateWithFlags(&s_b,   cudaStreamNonBlocking);
        cudaEventCreateWithFlags(&evFork, cudaEventDisableTiming);
        cudaEventCreateWithFlags(&evIns,  cudaEventDisableTiming);
        cudaEventCreateWithFlags(&evSB,   cudaEventDisableTiming);
        cudaFuncSetAttribute(k_simfocal, cudaFuncAttributeMaxDynamicSharedMemorySize, SIM_SMEM);
    }

    k_scatter<<<NS / 256, 256>>>(labels, labels2, inputs, indexes);
    cudaEventRecord(evFork, 0);

    // ins branch
    cudaStreamWaitEvent(s_ins, evFork, 0);
    k_ins<<<NB, 512, 0, s_ins>>>(inputs, features);
    cudaEventRecord(evIns, s_ins);

    // branch B: classes [1008, 2000), groups [63, 125)
    cudaStreamWaitEvent(s_b, evFork, 0);
    k_centroid<<<NGRP_B * GC, 512, 0, s_b>>>(features, NGRP_A * GC);
    k_simfocal<<<2 * NGRP_B, 256, SIM_SMEM, s_b>>>(NGRP_A);
    cudaEventRecord(evSB, s_b);

    // branch A: classes [0, 1008), groups [0, 63) on default stream
    k_centroid<<<NGRP_A * GC, 512>>>(features, 0);
    k_simfocal<<<2 * NGRP_A, 256, SIM_SMEM>>>(0);

    // join + final combine
    cudaStreamWaitEvent(0, evSB, 0);
    cudaStreamWaitEvent(0, evIns, 0);
    k_final<<<1, 256>>>(inputs, mask_in, epoch_p, back_p, out);
}